// round 8
// baseline (speedup 1.0000x reference)
#include <cuda_runtime.h>
#include <math.h>

// TV loss over x:(3, 4096, 4096) fp32 -> scalar sqrt(sum(dx^2)+sum(dy^2))
// Single fused kernel, one full wave (1176 blocks), balanced row ranges,
// 2-row unrolled mainloop. Neighbor column obtained via shfl (lane31: 1-lane LDG)
// instead of a per-thread scalar sidecar load.

#define W 4096
#define H 4096
#define CH 3
#define THREADS 256            // 256 threads * 4 floats = 1024 columns per block
#define GRID_X (W / (THREADS * 4))   // 4 column stripes
#define NGROUPS 98                   // 4*98*3 = 1176 blocks <= 1184 (one wave @ 8/SM)
#define NUM_BLOCKS (GRID_X * NGROUPS * CH)
#define BASE_ROWS (H - 1)            // base rows 0..4094

__device__ unsigned long long g_acc_bits = 0ull;   // double accumulator as bits
__device__ unsigned int g_count = 0;

// x[row][c4+4]: lane t+1's v.x via shfl; lane 31 loads the single float.
__device__ __forceinline__ float neighbor_ext(const float4& v, const float* p,
                                              bool last_col, int lane) {
    float nbr = __shfl_down_sync(0xFFFFFFFFu, v.x, 1);
    if (lane == 31)
        nbr = last_col ? 0.0f : p[4];
    return nbr;
}

// accumulate dx^2 into a0 and dy^2 into a1 for this thread's 4 columns
__device__ __forceinline__ void tv_accum(float& a0, float& a1, const float4& cur,
                                         float curext, const float4& nxt, bool last_col) {
    float d0 = cur.y - cur.x;
    float d1 = cur.z - cur.y;
    float d2 = cur.w - cur.z;
    a0 = fmaf(d0, d0, a0);
    a0 = fmaf(d1, d1, a0);
    a0 = fmaf(d2, d2, a0);
    float e0 = nxt.x - cur.x;
    float e1 = nxt.y - cur.y;
    float e2 = nxt.z - cur.z;
    a1 = fmaf(e0, e0, a1);
    a1 = fmaf(e1, e1, a1);
    a1 = fmaf(e2, e2, a1);
    if (!last_col) {
        float d3 = curext - cur.w;
        float e3 = nxt.w - cur.w;
        a0 = fmaf(d3, d3, a0);
        a1 = fmaf(e3, e3, a1);
    }
}

__global__ __launch_bounds__(THREADS, 8) void tv_fused_kernel(const float* __restrict__ x,
                                                              float* __restrict__ out) {
    const int ch   = blockIdx.z;
    const int c4   = (blockIdx.x * THREADS + threadIdx.x) * 4;
    const int g    = blockIdx.y;
    const int lane = threadIdx.x & 31;

    // balanced row range for group g
    const int row0 = (int)(((long long)g * BASE_ROWS) / NGROUPS);
    const int rend = (int)(((long long)(g + 1) * BASE_ROWS) / NGROUPS);

    const float* __restrict__ base = x + (size_t)ch * W * H;
    const bool last_col = (c4 == W - 4);   // only the true image edge column group

    float a0 = 0.0f, a1 = 0.0f;

    const float* p = base + (size_t)row0 * W + c4;
    float4 cur    = *(const float4*)p;
    float  curext = neighbor_ext(cur, p, last_col, lane);

    // ---- 2-row unrolled mainloop ----
    int i = row0;
    const int pair_end = row0 + ((rend - row0) & ~1);
    for (; i < pair_end; i += 2) {
        const float* p1 = base + (size_t)(i + 1) * W + c4;
        const float* p2 = base + (size_t)(i + 2) * W + c4;
        float4 n1 = *(const float4*)p1;
        float4 n2 = *(const float4*)p2;
        float n1ext = neighbor_ext(n1, p1, last_col, lane);
        float n2ext = neighbor_ext(n2, p2, last_col, lane);

        tv_accum(a0, a1, cur, curext, n1, last_col);
        tv_accum(a0, a1, n1, n1ext, n2, last_col);

        cur = n2;
        curext = n2ext;
    }
    if (i < rend) {    // odd trailing row
        const float* p1 = base + (size_t)(i + 1) * W + c4;
        float4 n1 = *(const float4*)p1;
        tv_accum(a0, a1, cur, curext, n1, last_col);
    }

    float acc = a0 + a1;

    // ---- block reduction ----
    #pragma unroll
    for (int off = 16; off > 0; off >>= 1)
        acc += __shfl_down_sync(0xFFFFFFFFu, acc, off);

    __shared__ float warp_sums[THREADS / 32];
    __shared__ bool is_last;
    const int wid = threadIdx.x >> 5;
    if (lane == 0) warp_sums[wid] = acc;
    __syncthreads();

    if (wid == 0) {
        float v = (lane < THREADS / 32) ? warp_sums[lane] : 0.0f;
        #pragma unroll
        for (int off = 4; off > 0; off >>= 1)
            v += __shfl_down_sync(0xFFFFFFFFu, v, off);
        if (lane == 0) {
            atomicAdd((double*)&g_acc_bits, (double)v);
            __threadfence();
            unsigned int ticket = atomicInc(&g_count, NUM_BLOCKS - 1);
            is_last = (ticket == NUM_BLOCKS - 1);   // wraps to 0 for next replay
        }
    }
    __syncthreads();

    // Last block finalizes: read+reset accumulator, write sqrt.
    if (is_last && threadIdx.x == 0) {
        unsigned long long bits = atomicExch(&g_acc_bits, 0ull);
        double total = __longlong_as_double(bits);
        out[0] = (float)sqrt(total);
    }
}

extern "C" void kernel_launch(void* const* d_in, const int* in_sizes, int n_in,
                              void* d_out, int out_size) {
    const float* x = (const float*)d_in[0];
    float* out = (float*)d_out;

    dim3 grid(GRID_X, NGROUPS, CH);
    tv_fused_kernel<<<grid, THREADS>>>(x, out);
}

// round 9
// speedup vs baseline: 1.0187x; 1.0187x over previous
#include <cuda_runtime.h>
#include <math.h>

// TV loss over x:(3, 4096, 4096) fp32 -> scalar sqrt(sum(dx^2)+sum(dy^2))
// Single fused kernel, one full wave (1176 blocks), balanced row ranges,
// 2-row unrolled mainloop, per-thread sidecar load for the cross-thread dx.
// Finalize: contention-free per-block partial stores + last-block parallel
// reduction (replaces 1176 serialized same-address fp64 atomics).

#define W 4096
#define H 4096
#define CH 3
#define THREADS 256            // 256 threads * 4 floats = 1024 columns per block
#define GRID_X (W / (THREADS * 4))   // 4 column stripes
#define NGROUPS 98                   // 4*98*3 = 1176 blocks <= 1184 (one wave @ 8/SM)
#define NUM_BLOCKS (GRID_X * NGROUPS * CH)
#define BASE_ROWS (H - 1)            // base rows 0..4094

__device__ double g_partials[NUM_BLOCKS];
__device__ unsigned int g_count = 0;

// accumulate dx^2 into a0 and dy^2 into a1 for this thread's 4 columns
__device__ __forceinline__ void tv_accum(float& a0, float& a1, const float4& cur,
                                         float curext, const float4& nxt, bool last_col) {
    float d0 = cur.y - cur.x;
    float d1 = cur.z - cur.y;
    float d2 = cur.w - cur.z;
    a0 = fmaf(d0, d0, a0);
    a0 = fmaf(d1, d1, a0);
    a0 = fmaf(d2, d2, a0);
    float e0 = nxt.x - cur.x;
    float e1 = nxt.y - cur.y;
    float e2 = nxt.z - cur.z;
    a1 = fmaf(e0, e0, a1);
    a1 = fmaf(e1, e1, a1);
    a1 = fmaf(e2, e2, a1);
    if (!last_col) {
        float d3 = curext - cur.w;
        float e3 = nxt.w - cur.w;
        a0 = fmaf(d3, d3, a0);
        a1 = fmaf(e3, e3, a1);
    }
}

__global__ __launch_bounds__(THREADS, 8) void tv_fused_kernel(const float* __restrict__ x,
                                                              float* __restrict__ out) {
    const int ch  = blockIdx.z;
    const int c4  = (blockIdx.x * THREADS + threadIdx.x) * 4;
    const int g   = blockIdx.y;

    // balanced row range for group g
    const int row0 = (int)(((long long)g * BASE_ROWS) / NGROUPS);
    const int rend = (int)(((long long)(g + 1) * BASE_ROWS) / NGROUPS);

    const float* __restrict__ base = x + (size_t)ch * W * H;
    const bool last_col = (c4 == W - 4);   // j=4095 excluded entirely

    float a0 = 0.0f, a1 = 0.0f;

    const float* p = base + (size_t)row0 * W + c4;
    float4 cur    = *(const float4*)p;
    float  curext = last_col ? 0.0f : p[4];

    // ---- 2-row unrolled mainloop ----
    int i = row0;
    const int pair_end = row0 + ((rend - row0) & ~1);
    for (; i < pair_end; i += 2) {
        const float* p1 = base + (size_t)(i + 1) * W + c4;
        const float* p2 = base + (size_t)(i + 2) * W + c4;
        float4 n1 = *(const float4*)p1;
        float4 n2 = *(const float4*)p2;
        float n1ext = last_col ? 0.0f : p1[4];
        float n2ext = last_col ? 0.0f : p2[4];

        tv_accum(a0, a1, cur, curext, n1, last_col);
        tv_accum(a0, a1, n1, n1ext, n2, last_col);

        cur = n2;
        curext = n2ext;
    }
    if (i < rend) {    // odd trailing row
        const float* p1 = base + (size_t)(i + 1) * W + c4;
        float4 n1 = *(const float4*)p1;
        tv_accum(a0, a1, cur, curext, n1, last_col);
    }

    float acc = a0 + a1;

    // ---- block reduction (fp32 shuffles) ----
    #pragma unroll
    for (int off = 16; off > 0; off >>= 1)
        acc += __shfl_down_sync(0xFFFFFFFFu, acc, off);

    __shared__ float warp_sums[THREADS / 32];
    __shared__ bool is_last;
    const int lane = threadIdx.x & 31;
    const int wid  = threadIdx.x >> 5;
    if (lane == 0) warp_sums[wid] = acc;
    __syncthreads();

    if (wid == 0) {
        float v = (lane < THREADS / 32) ? warp_sums[lane] : 0.0f;
        #pragma unroll
        for (int off = 4; off > 0; off >>= 1)
            v += __shfl_down_sync(0xFFFFFFFFu, v, off);
        if (lane == 0) {
            const int bid = (blockIdx.z * NGROUPS + blockIdx.y) * GRID_X + blockIdx.x;
            g_partials[bid] = (double)v;          // contention-free store
            __threadfence();                       // partial visible before ticket
            unsigned int ticket = atomicInc(&g_count, NUM_BLOCKS - 1);
            is_last = (ticket == NUM_BLOCKS - 1);  // wraps to 0 for next replay
        }
    }
    __syncthreads();

    // ---- last block reduces all partials in parallel ----
    if (is_last) {
        __threadfence();   // acquire: see all writers' partials
        double s = 0.0;
        for (int k = threadIdx.x; k < NUM_BLOCKS; k += THREADS)
            s += g_partials[k];

        #pragma unroll
        for (int off = 16; off > 0; off >>= 1)
            s += __shfl_down_sync(0xFFFFFFFFu, s, off);

        __shared__ double dsum[THREADS / 32];
        if (lane == 0) dsum[wid] = s;
        __syncthreads();

        if (wid == 0) {
            double v = (lane < THREADS / 32) ? dsum[lane] : 0.0;
            #pragma unroll
            for (int off = 4; off > 0; off >>= 1)
                v += __shfl_down_sync(0xFFFFFFFFu, v, off);
            if (lane == 0)
                out[0] = (float)sqrt(v);
        }
    }
}

extern "C" void kernel_launch(void* const* d_in, const int* in_sizes, int n_in,
                              void* d_out, int out_size) {
    const float* x = (const float*)d_in[0];
    float* out = (float*)d_out;

    dim3 grid(GRID_X, NGROUPS, CH);
    tv_fused_kernel<<<grid, THREADS>>>(x, out);
}

// round 10
// speedup vs baseline: 1.0782x; 1.0584x over previous
#include <cuda_runtime.h>
#include <math.h>

// TV loss over x:(3, 4096, 4096) fp32 -> scalar sqrt(sum(dx^2)+sum(dy^2))
// Full-row blocks: 1024 threads * float4 = 4096 cols, so each block streams a
// CONTIGUOUS multi-row region (best DRAM locality). One full wave: 294 blocks
// (98 balanced row groups x 3 channels) at 2 blocks/SM. 2-row unrolled mainloop,
// per-thread sidecar load, atomic+ticket finalize (best measured, R7).

#define W 4096
#define H 4096
#define CH 3
#define THREADS 1024           // 1024 threads * 4 floats = full 4096-col row
#define NGROUPS 98             // 98*3 = 294 blocks <= 296 (one wave @ 2/SM)
#define NUM_BLOCKS (NGROUPS * CH)
#define BASE_ROWS (H - 1)      // base rows 0..4094

__device__ unsigned long long g_acc_bits = 0ull;   // double accumulator as bits
__device__ unsigned int g_count = 0;

// accumulate dx^2 into a0 and dy^2 into a1 for this thread's 4 columns
__device__ __forceinline__ void tv_accum(float& a0, float& a1, const float4& cur,
                                         float curext, const float4& nxt, bool last_col) {
    float d0 = cur.y - cur.x;
    float d1 = cur.z - cur.y;
    float d2 = cur.w - cur.z;
    a0 = fmaf(d0, d0, a0);
    a0 = fmaf(d1, d1, a0);
    a0 = fmaf(d2, d2, a0);
    float e0 = nxt.x - cur.x;
    float e1 = nxt.y - cur.y;
    float e2 = nxt.z - cur.z;
    a1 = fmaf(e0, e0, a1);
    a1 = fmaf(e1, e1, a1);
    a1 = fmaf(e2, e2, a1);
    if (!last_col) {
        float d3 = curext - cur.w;
        float e3 = nxt.w - cur.w;
        a0 = fmaf(d3, d3, a0);
        a1 = fmaf(e3, e3, a1);
    }
}

__global__ __launch_bounds__(THREADS, 2) void tv_fused_kernel(const float* __restrict__ x,
                                                              float* __restrict__ out) {
    const int ch = blockIdx.z;
    const int g  = blockIdx.y;
    const int c4 = threadIdx.x * 4;                 // this thread's column base

    // balanced row range for group g
    const int row0 = (int)(((long long)g * BASE_ROWS) / NGROUPS);
    const int rend = (int)(((long long)(g + 1) * BASE_ROWS) / NGROUPS);

    const float* __restrict__ base = x + (size_t)ch * W * H;
    const bool last_col = (threadIdx.x == THREADS - 1);   // cols 4092..4095

    float a0 = 0.0f, a1 = 0.0f;

    const float* p = base + (size_t)row0 * W + c4;
    float4 cur    = *(const float4*)p;
    float  curext = last_col ? 0.0f : p[4];

    // ---- 2-row unrolled mainloop over contiguous rows ----
    int i = row0;
    const int pair_end = row0 + ((rend - row0) & ~1);
    for (; i < pair_end; i += 2) {
        const float* p1 = base + (size_t)(i + 1) * W + c4;
        const float* p2 = base + (size_t)(i + 2) * W + c4;
        float4 n1 = *(const float4*)p1;
        float4 n2 = *(const float4*)p2;
        float n1ext = last_col ? 0.0f : p1[4];
        float n2ext = last_col ? 0.0f : p2[4];

        tv_accum(a0, a1, cur, curext, n1, last_col);
        tv_accum(a0, a1, n1, n1ext, n2, last_col);

        cur = n2;
        curext = n2ext;
    }
    if (i < rend) {    // odd trailing row
        const float* p1 = base + (size_t)(i + 1) * W + c4;
        float4 n1 = *(const float4*)p1;
        tv_accum(a0, a1, cur, curext, n1, last_col);
    }

    float acc = a0 + a1;

    // ---- block reduction ----
    #pragma unroll
    for (int off = 16; off > 0; off >>= 1)
        acc += __shfl_down_sync(0xFFFFFFFFu, acc, off);

    __shared__ float warp_sums[THREADS / 32];
    __shared__ bool is_last;
    const int lane = threadIdx.x & 31;
    const int wid  = threadIdx.x >> 5;
    if (lane == 0) warp_sums[wid] = acc;
    __syncthreads();

    if (wid == 0) {
        float v = (lane < THREADS / 32) ? warp_sums[lane] : 0.0f;
        #pragma unroll
        for (int off = 16; off > 0; off >>= 1)
            v += __shfl_down_sync(0xFFFFFFFFu, v, off);
        if (lane == 0) {
            atomicAdd((double*)&g_acc_bits, (double)v);
            __threadfence();
            unsigned int ticket = atomicInc(&g_count, NUM_BLOCKS - 1);
            is_last = (ticket == NUM_BLOCKS - 1);   // wraps to 0 for next replay
        }
    }
    __syncthreads();

    // Last block finalizes: read+reset accumulator, write sqrt.
    if (is_last && threadIdx.x == 0) {
        unsigned long long bits = atomicExch(&g_acc_bits, 0ull);
        double total = __longlong_as_double(bits);
        out[0] = (float)sqrt(total);
    }
}

extern "C" void kernel_launch(void* const* d_in, const int* in_sizes, int n_in,
                              void* d_out, int out_size) {
    const float* x = (const float*)d_in[0];
    float* out = (float*)d_out;

    dim3 grid(1, NGROUPS, CH);
    tv_fused_kernel<<<grid, THREADS>>>(x, out);
}